// round 3
// baseline (speedup 1.0000x reference)
#include <cuda_runtime.h>

// TokenEmbedding segment-sum, two-phase:
//   Phase A: scatter segment boundaries  start[b][t] = lower_bound(w2t[b], t)
//   Phase B: one CTA per (b, t0..t0+3): the 4 tokens' wordpiece ranges are
//            adjacent, so the block streams ONE contiguous row range and
//            routes each row into one of 4 register accumulators by
//            predicated compare. 4x work per block -> amortized metadata,
//            higher load MLP, fewer blocks.

#define B_DIM 8
#define L_DIM 4096
#define H_DIM 1024
#define H4 (H_DIM / 4)   // 256 float4 per row == blockDim.x of phase B
#define TPB 4            // tokens per block in phase B

// scratch: segment start offsets, one extra slot per batch for the end sentinel
__device__ int g_seg_start[B_DIM][L_DIM + 1];

__global__ __launch_bounds__(256) void seg_bounds_kernel(
    const int* __restrict__ w2t)      // [B, L] sorted per row
{
    const int b = blockIdx.y;
    const int w = blockIdx.x * blockDim.x + threadIdx.x;
    if (w >= L_DIM) return;

    const int* idx = w2t + (size_t)b * L_DIM;
    const int cur  = __ldg(idx + w);
    const int prev = (w > 0) ? __ldg(idx + w - 1) : -1;

    // start[t] = w for every token t in (prev, cur]
    for (int t = prev + 1; t <= cur; ++t)
        g_seg_start[b][t] = w;

    // tail: tokens beyond the last wordpiece's token map to empty [L, L)
    if (w == L_DIM - 1) {
        for (int t = cur + 1; t <= L_DIM; ++t)
            g_seg_start[b][t] = L_DIM;
    }
}

__global__ __launch_bounds__(H4) void token_segsum_kernel(
    const float* __restrict__ x,      // [B, L, H]
    float*       __restrict__ out)    // [B, L, H]
{
    const int t0 = blockIdx.x * TPB;  // first token of this block
    const int b  = blockIdx.y;        // batch

    __shared__ int s_bnd[TPB + 1];
    if (threadIdx.x <= TPB)
        s_bnd[threadIdx.x] = g_seg_start[b][t0 + threadIdx.x];
    __syncthreads();

    const int s0 = s_bnd[0];
    const int s1 = s_bnd[1];
    const int s2 = s_bnd[2];
    const int s3 = s_bnd[3];
    const int s4 = s_bnd[4];

    const int c = threadIdx.x;  // float4 column 0..255
    const float4* __restrict__ rows =
        reinterpret_cast<const float4*>(x + (size_t)b * L_DIM * H_DIM);

    float4 a0 = make_float4(0.f, 0.f, 0.f, 0.f);
    float4 a1 = a0, a2 = a0, a3 = a0;

    #pragma unroll 2
    for (int w = s0; w < s4; ++w) {
        float4 v = __ldg(&rows[(size_t)w * H4 + c]);
        const int k = (w >= s1) + (w >= s2) + (w >= s3);
        if (k == 0)      { a0.x += v.x; a0.y += v.y; a0.z += v.z; a0.w += v.w; }
        else if (k == 1) { a1.x += v.x; a1.y += v.y; a1.z += v.z; a1.w += v.w; }
        else if (k == 2) { a2.x += v.x; a2.y += v.y; a2.z += v.z; a2.w += v.w; }
        else             { a3.x += v.x; a3.y += v.y; a3.z += v.z; a3.w += v.w; }
    }

    float4* __restrict__ orow =
        reinterpret_cast<float4*>(out + ((size_t)b * L_DIM + t0) * H_DIM);
    orow[c]          = a0;
    orow[H4 + c]     = a1;
    orow[2 * H4 + c] = a2;
    orow[3 * H4 + c] = a3;
}

extern "C" void kernel_launch(void* const* d_in, const int* in_sizes, int n_in,
                              void* d_out, int out_size)
{
    const float* x   = (const float*)d_in[0];   // sequence_output [B,L,H] fp32
    const int*   w2t = (const int*)  d_in[1];   // wordpiece_to_token [B,L] int32
    float*       out = (float*)d_out;           // [B,L,H] fp32

    dim3 gridA(L_DIM / 256, B_DIM);
    seg_bounds_kernel<<<gridA, 256>>>(w2t);

    dim3 gridB(L_DIM / TPB, B_DIM);
    token_segsum_kernel<<<gridB, H4>>>(x, out);
}

// round 4
// speedup vs baseline: 1.2267x; 1.2267x over previous
#include <cuda_runtime.h>

// TokenEmbedding segment-sum, two-phase:
//   Phase A: scatter segment boundaries  start[b][t] = lower_bound(w2t[b], t)
//   Phase B: one CTA per (b, t), 128 threads; each thread owns TWO float4
//            columns (c and c+128) -> two guaranteed-independent loads per
//            row, doubling load MLP vs one-column-per-thread, at only one
//            extra accumulator of register cost. Rows/outputs are touched
//            exactly once -> __ldcs/__stcs to keep boundary metadata L2-hot.

#define B_DIM 8
#define L_DIM 4096
#define H_DIM 1024
#define H4 (H_DIM / 4)     // 256 float4 per row
#define TB  128            // phase-B threads: each covers 2 float4 columns

// scratch: segment start offsets, one extra slot per batch for the end sentinel
__device__ int g_seg_start[B_DIM][L_DIM + 1];

__global__ __launch_bounds__(256) void seg_bounds_kernel(
    const int* __restrict__ w2t)      // [B, L] sorted per row
{
    const int b = blockIdx.y;
    const int w = blockIdx.x * blockDim.x + threadIdx.x;
    if (w >= L_DIM) return;

    const int* idx = w2t + (size_t)b * L_DIM;
    const int cur  = __ldg(idx + w);
    const int prev = (w > 0) ? __ldg(idx + w - 1) : -1;

    // start[t] = w for every token t in (prev, cur]
    for (int t = prev + 1; t <= cur; ++t)
        g_seg_start[b][t] = w;

    // tail: tokens beyond the last wordpiece's token map to empty [L, L)
    if (w == L_DIM - 1) {
        for (int t = cur + 1; t <= L_DIM; ++t)
            g_seg_start[b][t] = L_DIM;
    }
}

__global__ __launch_bounds__(TB) void token_segsum_kernel(
    const float* __restrict__ x,      // [B, L, H]
    float*       __restrict__ out)    // [B, L, H]
{
    const int t = blockIdx.x;   // token id
    const int b = blockIdx.y;   // batch

    // broadcast metadata loads (issue back-to-back, independent; L2-hot)
    const int lo = __ldg(&g_seg_start[b][t]);
    const int hi = __ldg(&g_seg_start[b][t + 1]);

    const int c = threadIdx.x;  // float4 column 0..127 (also owns c+128)
    const float4* __restrict__ rows =
        reinterpret_cast<const float4*>(x + (size_t)b * L_DIM * H_DIM);

    float4 a0 = make_float4(0.f, 0.f, 0.f, 0.f);
    float4 a1 = a0;

    for (int w = lo; w < hi; ++w) {
        const float4* r = rows + (size_t)w * H4;
        float4 v0 = __ldcs(r + c);
        float4 v1 = __ldcs(r + c + TB);
        a0.x += v0.x; a0.y += v0.y; a0.z += v0.z; a0.w += v0.w;
        a1.x += v1.x; a1.y += v1.y; a1.z += v1.z; a1.w += v1.w;
    }

    float4* __restrict__ orow =
        reinterpret_cast<float4*>(out + ((size_t)b * L_DIM + t) * H_DIM);
    __stcs(orow + c,      a0);
    __stcs(orow + c + TB, a1);
}

extern "C" void kernel_launch(void* const* d_in, const int* in_sizes, int n_in,
                              void* d_out, int out_size)
{
    const float* x   = (const float*)d_in[0];   // sequence_output [B,L,H] fp32
    const int*   w2t = (const int*)  d_in[1];   // wordpiece_to_token [B,L] int32
    float*       out = (float*)d_out;           // [B,L,H] fp32

    dim3 gridA(L_DIM / 256, B_DIM);
    seg_bounds_kernel<<<gridA, 256>>>(w2t);

    dim3 gridB(L_DIM, B_DIM);
    token_segsum_kernel<<<gridB, TB>>>(x, out);
}